// round 12
// baseline (speedup 1.0000x reference)
#include <cuda_runtime.h>

// x shape (N=2, D=192, H=256, W=512), float32.
#define DIMD 192
#define HWD  131072          // H*W
#define BLK  128
#define NPIX 262144          // N*H*W
#define SMEM_BYTES (DIMD * BLK * 4)   // 96 KB -> 2 CTAs/SM

// Correctly-rounded a/5 via Markstein final step with exact seed y=RN(1/5).
// Bit-identical to __fdiv_rn(a,5) for all normal a (proven IEEE sequence),
// 3 FMA-pipe ops instead of MUFU.RCP + fixup chain. Inputs here are in [0,5].
__device__ __forceinline__ float qdiv5(float a)
{
    const float y  = 0.2f;              // RN(1/5)
    float q0 = a * y;                   // RN(a*y)
    float r  = fmaf(-5.0f, q0, a);      // exact residual (fma)
    return fmaf(r, y, q0);              // RN(a/5)
}

// Blur at depth d from raw x in smem (exact reference add order, zero-padded),
// with optional interval [ZA,ZB] zeroed AFTER the blur (x_blur * ~mask).
template<bool HASZ>
__device__ __forceinline__ float blur_at(const float* __restrict__ sp, int d,
                                         int ZA, int ZB)
{
    if (HASZ && (d >= ZA && d <= ZB)) return 0.0f;
    float a = (d >= 2)        ? sp[(d - 2) * BLK] : 0.0f;
    a = a + ((d >= 1)         ? sp[(d - 1) * BLK] : 0.0f);
    a = a +                     sp[d * BLK];
    a = a + ((d + 1 < DIMD)   ? sp[(d + 1) * BLK] : 0.0f);
    a = a + ((d + 2 < DIMD)   ? sp[(d + 2) * BLK] : 0.0f);
    return qdiv5(a);
}

// Right/left slope scans from argmax -> modal interval [lo,hi].
template<bool HASZ>
__device__ __forceinline__ void scans(const float* __restrict__ sp, int idx, float bq,
                                      int ZA, int ZB, int& lo, int& hi)
{
    int i = idx + 1;
    float bprev = bq;
    while (i < DIMD) {
        float bi = blur_at<HASZ>(sp, i, ZA, ZB);
        if (bi > bprev) break;                  // first diff > 0 after idx
        bprev = bi; ++i;
    }
    const int ir = i - 1;                       // i==D: sentinel fires -> D-1

    i = idx;
    float bcur = bq;
    while (i >= 1) {
        float bm = blur_at<HASZ>(sp, i - 1, ZA, ZB);
        if (bcur < bm) break;                   // last diff < 0 at/below idx
        bcur = bm; --i;
    }
    const int il = i;                           // i==0: sentinel fires

    int dev = 2 * idx - ir - il; if (dev < 0) dev = -dev;
    if (dev < 3) { lo = il; hi = ir; }
    else {
        int rr = min(ir - idx, idx - il);
        lo = idx - rr; hi = idx + rr;
    }
}

// Continue argmax of blur(raw x) over d in [a, bEnd). (Blur always uses raw x:
// the reference zeroes AFTER blurring, and zeros can never win vs positives.)
__device__ __forceinline__ void seg_argmax(const float* __restrict__ sp, int a, int bEnd,
                                           float& bestQ, int& idx)
{
    float xm2 = (a - 2 >= 0)   ? sp[(a - 2) * BLK] : 0.0f;
    float xm1 = (a - 1 >= 0)   ? sp[(a - 1) * BLK] : 0.0f;
    float x0  =                  sp[a * BLK];
    float x1  = (a + 1 < DIMD) ? sp[(a + 1) * BLK] : 0.0f;
    #pragma unroll 4
    for (int d = a; d < bEnd; ++d) {
        float x2  = (d + 2 < DIMD) ? sp[(d + 2) * BLK] : 0.0f;
        float q   = qdiv5((((xm2 + xm1) + x0) + x1) + x2);
        bool  u   = (q > bestQ);                // strict -> first occurrence
        bestQ = u ? q : bestQ;
        idx   = u ? d : idx;
        xm2 = xm1; xm1 = x0; x0 = x1; x1 = x2;
    }
}

__global__ void __launch_bounds__(BLK, 2)
dme_kernel(const float* __restrict__ x, float* __restrict__ out)
{
    extern __shared__ float s[];                // [DIMD][BLK]
    const int tid  = threadIdx.x;
    const int pix0 = blockIdx.x * BLK;          // blocks never straddle n
    const int n    = pix0 >> 17;                // / HWD
    const int hw0  = pix0 & (HWD - 1);
    const float* __restrict__ gb = x + (size_t)n * DIMD * HWD + hw0;

    // ---- cooperative vectorized stage-in: 6144 float4s per block,
    //      48 LDG.128 + STS.128 per thread, fully independent (high MLP) ----
    #pragma unroll 8
    for (int i = 0; i < (DIMD * BLK / 4) / BLK; ++i) {   // 48 iters
        int flat = i * BLK + tid;               // float4 index, 32 per d-row
        int d    = flat >> 5;
        int p4   = flat & 31;
        float4 v = *(const float4*)(gb + (size_t)d * HWD + p4 * 4);
        *(float4*)(&s[d * BLK + p4 * 4]) = v;
    }
    __syncthreads();

    const float* __restrict__ sp = s + tid;     // lane-private bank column

    // ---- pass-1 argmax over blur (rolling window, 1 LDS/iter) ----
    float bestQ = -1.0f; int idx = 0;
    {
        float xm2 = 0.0f, xm1 = 0.0f, x0 = sp[0], x1 = sp[BLK];
        #pragma unroll 4
        for (int d = 0; d < DIMD; ++d) {
            float x2 = (d + 2 < DIMD) ? sp[(d + 2) * BLK] : 0.0f;
            float q  = qdiv5((((xm2 + xm1) + x0) + x1) + x2);
            bool  u  = (q > bestQ);
            bestQ = u ? q : bestQ;
            idx   = u ? d : idx;
            xm2 = xm1; xm1 = x0; x0 = x1; x1 = x2;
        }
    }

    int lo1, hi1;
    scans<false>(sp, idx, bestQ, 0, -1, lo1, hi1);

    // ---- pass-2 argmax over the complement of [lo1,hi1] only ----
    float bq2 = -1.0f; int idx2 = 0;
    if (lo1 > 0)        seg_argmax(sp, 0, lo1, bq2, idx2);
    if (hi1 < DIMD - 1) seg_argmax(sp, hi1 + 1, DIMD, bq2, idx2);
    int lo2, hi2;
    scans<true>(sp, idx2, bq2, lo1, hi1, lo2, hi2);

    // ---- narrow final reductions: y on [lo1,hi1], z on [lo2,hi2] \ [lo1,hi1] ----
    float sy = 0.0f, syd = 0.0f, sz = 0.0f, szd = 0.0f;
    for (int d = lo1; d <= hi1; ++d) {
        float v = sp[d * BLK];
        sy += v; syd = fmaf(v, (float)d, syd);
    }
    for (int d = lo2; d <= hi2; ++d) {
        if (d >= lo1 && d <= hi1) continue;
        float v = sp[d * BLK];
        sz += v; szd = fmaf(v, (float)d, szd);
    }

    const bool  py  = (sy >= sz);
    const float num = py ? syd : szd;
    const float den = py ? sy  : sz;            // > 0 guaranteed (x > 0)
    out[pix0 + tid] = __fdiv_rn(num, den);
}

extern "C" void kernel_launch(void* const* d_in, const int* in_sizes, int n_in,
                              void* d_out, int out_size)
{
    const float* x   = (const float*)d_in[0];
    float*       out = (float*)d_out;

    cudaFuncSetAttribute(dme_kernel,
                         cudaFuncAttributeMaxDynamicSharedMemorySize, SMEM_BYTES);

    dme_kernel<<<NPIX / BLK, BLK, SMEM_BYTES>>>(x, out);
}

// round 13
// speedup vs baseline: 1.2271x; 1.2271x over previous
#include <cuda_runtime.h>

// x shape (N=2, D=192, H=256, W=512), float32.
#define DIMD 192
#define HWD  131072          // H*W
#define BLK  256             // threads per block
#define COLS 128             // pixel columns per block (2 threads / column)
#define NPIX 262144          // N*H*W
#define CST  128             // smem column stride (floats)
#define SMEM_BYTES (DIMD * COLS * 4)   // 96 KB -> 2 CTAs/SM (16 warps/SM)

// Correctly-rounded a/5 (Markstein step, exact seed 0.2f) — bit-identical to
// __fdiv_rn(a,5) for the inputs here; 3 FMA-pipe ops. Validated rounds 5-12.
__device__ __forceinline__ float qdiv5(float a)
{
    const float y  = 0.2f;
    float q0 = a * y;
    float r  = fmaf(-5.0f, q0, a);
    return fmaf(r, y, q0);
}

// Rolling right+left slope scans from argmax -> modal interval [lo,hi].
// Blur uses raw x (exact reference add order, zero padding); HASZ zeroes the
// blur VALUE on [ZA,ZB] (x_blur * ~mask semantics). 1 LDS per step.
template<bool HASZ>
__device__ __forceinline__ void scans(const float* __restrict__ sp, int idx, float bq,
                                      int ZA, int ZB, int& lo, int& hi)
{
    // right scan: first strictly-increasing step after idx
    int ir;
    {
        int i = idx + 1;
        float bprev = bq;
        if (i < DIMD) {
            float w0 = (i >= 2) ? sp[(i - 2) * CST] : 0.0f;
            float w1 = sp[(i - 1) * CST];
            float w2 = sp[i * CST];
            float w3 = (i + 1 < DIMD) ? sp[(i + 1) * CST] : 0.0f;
            while (true) {
                float w4 = (i + 2 < DIMD) ? sp[(i + 2) * CST] : 0.0f;
                float q  = qdiv5((((w0 + w1) + w2) + w3) + w4);
                if (HASZ && i >= ZA && i <= ZB) q = 0.0f;
                if (q > bprev) break;
                bprev = q; ++i;
                if (i >= DIMD) break;
                w0 = w1; w1 = w2; w2 = w3; w3 = w4;
            }
        }
        ir = i - 1;                         // i==D: sentinel fires -> D-1
    }

    // left scan: last strictly-decreasing step at/below idx
    int il;
    {
        int i = idx;
        float bcur = bq;
        if (i >= 1) {
            float v0 = (i >= 3) ? sp[(i - 3) * CST] : 0.0f;
            float v1 = (i >= 2) ? sp[(i - 2) * CST] : 0.0f;
            float v2 = sp[(i - 1) * CST];
            float v3 = sp[i * CST];
            float v4 = (i + 1 < DIMD) ? sp[(i + 1) * CST] : 0.0f;
            while (true) {
                float q = qdiv5((((v0 + v1) + v2) + v3) + v4);   // blur at i-1
                if (HASZ && (i - 1) >= ZA && (i - 1) <= ZB) q = 0.0f;
                if (bcur < q) break;
                bcur = q; --i;
                if (i < 1) break;
                v4 = v3; v3 = v2; v2 = v1; v1 = v0;
                v0 = (i >= 3) ? sp[(i - 3) * CST] : 0.0f;
            }
        }
        il = i;                             // i==0: sentinel fires
    }

    int dev = 2 * idx - ir - il; if (dev < 0) dev = -dev;
    if (dev < 3) { lo = il; hi = ir; }
    else {
        int rr = min(ir - idx, idx - il);
        lo = idx - rr; hi = idx + rr;
    }
}

// Continue argmax of blur(raw x) over d in [a, bEnd), rolling window.
__device__ __forceinline__ void seg_argmax(const float* __restrict__ sp, int a, int bEnd,
                                           float& bestQ, int& idx)
{
    if (a >= bEnd) return;
    float xm2 = (a - 2 >= 0)   ? sp[(a - 2) * CST] : 0.0f;
    float xm1 = (a - 1 >= 0)   ? sp[(a - 1) * CST] : 0.0f;
    float x0  =                  sp[a * CST];
    float x1  = (a + 1 < DIMD) ? sp[(a + 1) * CST] : 0.0f;
    #pragma unroll 2
    for (int d = a; d < bEnd; ++d) {
        float x2 = (d + 2 < DIMD) ? sp[(d + 2) * CST] : 0.0f;
        float q  = qdiv5((((xm2 + xm1) + x0) + x1) + x2);
        bool  u  = (q > bestQ);             // strict -> first occurrence
        bestQ = u ? q : bestQ;
        idx   = u ? d : idx;
        xm2 = xm1; xm1 = x0; x0 = x1; x1 = x2;
    }
}

// Merge (lowQ,lowI) with (highQ,highI) where all high indices > all low indices.
__device__ __forceinline__ void merge_lohi(float lq, int li, float hq, int hi_,
                                           float& q, int& i)
{
    bool u = (hq > lq);
    q = u ? hq : lq;
    i = u ? hi_ : li;
}

__global__ void __launch_bounds__(BLK, 2)
dme_kernel(const float* __restrict__ x, float* __restrict__ out)
{
    extern __shared__ float s[];                // [DIMD][COLS]
    const int tid  = threadIdx.x;
    const int c    = tid >> 1;                  // column 0..127
    const int r    = tid & 1;                   // role: 0 = low half, 1 = high half
    const int pix0 = blockIdx.x * COLS;         // blocks never straddle n
    const int n    = pix0 >> 17;                // / HWD
    const int hw0  = pix0 & (HWD - 1);
    const float* __restrict__ gb = x + (size_t)n * DIMD * HWD + hw0;

    // ---- cooperative vectorized stage-in: 6144 float4 per block, 24/thread ----
    #pragma unroll 8
    for (int i = 0; i < (DIMD * COLS / 4) / BLK; ++i) {   // 24 iters
        int flat = i * BLK + tid;               // float4 index, 32 per d-row
        int d    = flat >> 5;
        int p4   = flat & 31;
        float4 v = *(const float4*)(gb + (size_t)d * HWD + p4 * 4);
        *(float4*)(&s[d * COLS + p4 * 4]) = v;
    }
    __syncthreads();

    const float* __restrict__ sp = s + c;       // this column's base

    // ---- pass-1 argmax over blur: 2 blocked chains of 48 per role ----
    const int base0 = 96 * r;
    float bq[2]; int bi[2];
    float a2[2], a1[2], a0[2], ap[2];
    #pragma unroll
    for (int k = 0; k < 2; ++k) {
        int b = base0 + 48 * k;
        a2[k] = (b >= 2) ? sp[(b - 2) * CST] : 0.0f;
        a1[k] = (b >= 1) ? sp[(b - 1) * CST] : 0.0f;
        a0[k] = sp[b * CST];
        ap[k] = sp[(b + 1) * CST];
        bq[k] = -1.0f; bi[k] = 0;
    }
    #pragma unroll 2
    for (int j = 0; j < 46; ++j) {
        #pragma unroll
        for (int k = 0; k < 2; ++k) {
            int d = base0 + 48 * k + j;
            float x2 = sp[(d + 2) * CST];       // d+2 <= 191 here for all roles
            float q  = qdiv5((((a2[k] + a1[k]) + a0[k]) + ap[k]) + x2);
            bool  u  = (q > bq[k]);
            bq[k] = u ? q : bq[k];
            bi[k] = u ? d : bi[k];
            a2[k] = a1[k]; a1[k] = a0[k]; a0[k] = ap[k]; ap[k] = x2;
        }
    }
    #pragma unroll
    for (int k = 0; k < 2; ++k) {               // peeled j = 46, 47 (tail guards)
        #pragma unroll
        for (int j = 46; j < 48; ++j) {
            int d  = base0 + 48 * k + j;
            int i2 = d + 2;
            float x2 = (i2 < DIMD) ? sp[i2 * CST] : 0.0f;
            float q  = qdiv5((((a2[k] + a1[k]) + a0[k]) + ap[k]) + x2);
            bool  u  = (q > bq[k]);
            bq[k] = u ? q : bq[k];
            bi[k] = u ? d : bi[k];
            a2[k] = a1[k]; a1[k] = a0[k]; a0[k] = ap[k]; ap[k] = x2;
        }
    }
    // local merge (chain0 indices < chain1 indices), then cross-role merge
    float mq; int mi;
    merge_lohi(bq[0], bi[0], bq[1], bi[1], mq, mi);
    float oq = __shfl_xor_sync(0xffffffffu, mq, 1);
    int   oi = __shfl_xor_sync(0xffffffffu, mi, 1);
    float bestQ; int idx;
    merge_lohi(r ? oq : mq, r ? oi : mi, r ? mq : oq, r ? mi : oi, bestQ, idx);

    // ---- modal interval 1 (duplicated on both lanes: identical data/trips) ----
    int lo1, hi1;
    scans<false>(sp, idx, bestQ, 0, -1, lo1, hi1);

    // ---- pass-2 argmax over complement, split by role half [96r, 96r+96) ----
    const int R0 = base0, R1 = base0 + 96;
    float q2 = -1.0f; int i2x = 0;
    seg_argmax(sp, R0, min(lo1, R1), q2, i2x);            // below-interval part
    seg_argmax(sp, max(hi1 + 1, R0), R1, q2, i2x);        // above-interval part
    float oq2 = __shfl_xor_sync(0xffffffffu, q2, 1);
    int   oi2 = __shfl_xor_sync(0xffffffffu, i2x, 1);
    float bq2; int idx2;
    merge_lohi(r ? oq2 : q2, r ? oi2 : i2x, r ? q2 : oq2, r ? i2x : oi2, bq2, idx2);

    int lo2, hi2;
    scans<true>(sp, idx2, bq2, lo1, hi1, lo2, hi2);

    // ---- reductions, role-split into one generic loop ----
    // role0: y over [lo1,hi1] (no exclusion); role1: z over [lo2,hi2] \ [lo1,hi1]
    const int A  = r ? lo2 : lo1;
    const int B  = r ? hi2 : hi1;
    const int E0 = r ? lo1 : 1;
    const int E1 = r ? hi1 : 0;
    float ss = 0.0f, sd = 0.0f;
    for (int d = A; d <= B; ++d) {
        if (d >= E0 && d <= E1) continue;
        float v = sp[d * CST];
        ss += v; sd = fmaf(v, (float)d, sd);
    }
    float os = __shfl_xor_sync(0xffffffffu, ss, 1);
    float od = __shfl_xor_sync(0xffffffffu, sd, 1);
    const float sy  = r ? os : ss, syd = r ? od : sd;
    const float sz  = r ? ss : os, szd = r ? sd : od;

    if (r == 0) {
        const bool  py  = (sy >= sz);
        const float num = py ? syd : szd;
        const float den = py ? sy  : sz;        // > 0 guaranteed (x > 0)
        out[pix0 + c] = __fdiv_rn(num, den);
    }
}

extern "C" void kernel_launch(void* const* d_in, const int* in_sizes, int n_in,
                              void* d_out, int out_size)
{
    const float* x   = (const float*)d_in[0];
    float*       out = (float*)d_out;

    cudaFuncSetAttribute(dme_kernel,
                         cudaFuncAttributeMaxDynamicSharedMemorySize, SMEM_BYTES);

    dme_kernel<<<NPIX / COLS, BLK, SMEM_BYTES>>>(x, out);
}